// round 13
// baseline (speedup 1.0000x reference)
#include <cuda_runtime.h>
#include <cuda_bf16.h>
#include <cstdint>
#include <math.h>

#define Bb 16
#define Ss 512
#define Dd 768
#define Kc 8192
#define Hh 8
#define Ll 6
#define FFd 2048
#define NTOK 8192
#define DH 96
#define NEGB (-1e9f)
typedef __nv_bfloat16 bf16;

#define W_SAIN_N  (Ll * 3 * Dd * Dd)
#define W_SQ_N    (Ll * Dd * Dd)
#define W_FF1_N   (Ll * FFd * Dd)
#define W_FF2_N   (Ll * Dd * FFd)
#define W_OUT_N   (Dd * Dd)

// ---------------- scratch ----------------
__device__ __align__(256) float g_mem  [NTOK * Dd];
__device__ __align__(256) float g_h    [NTOK * Dd];
__device__ __align__(256) float g_tmp  [NTOK * Dd];
__device__ __align__(256) float g_dist [(size_t)NTOK * Kc];
__device__ float g_xnorm[NTOK];
__device__ float g_cnorm[Kc];
__device__ float g_padf [NTOK];
__device__ int   g_pad  [NTOK];
__device__ int   g_enc  [NTOK];

__device__ __align__(256) bf16 g_qkvh[NTOK*3*Dd], g_qkvl[NTOK*3*Dd];
__device__ __align__(256) bf16 g_h_h[NTOK*Dd],  g_h_l[NTOK*Dd];
__device__ __align__(256) bf16 g_att_h[NTOK*Dd],g_att_l[NTOK*Dd];
__device__ __align__(256) bf16 g_mem_h[NTOK*Dd],g_mem_l[NTOK*Dd];
__device__ __align__(256) bf16 g_cb_h[Kc*Dd],   g_cb_l[Kc*Dd];
__device__ __align__(256) bf16 g_ff_h[NTOK*FFd],g_ff_l[NTOK*FFd];
__device__ __align__(256) bf16 g_wsain_h[W_SAIN_N], g_wsain_l[W_SAIN_N];
__device__ __align__(256) bf16 g_wsaout_h[W_SQ_N],  g_wsaout_l[W_SQ_N];
__device__ __align__(256) bf16 g_wcain_h[W_SAIN_N], g_wcain_l[W_SAIN_N];
__device__ __align__(256) bf16 g_wcaout_h[W_SQ_N],  g_wcaout_l[W_SQ_N];
__device__ __align__(256) bf16 g_wff1_h[W_FF1_N],   g_wff1_l[W_FF1_N];
__device__ __align__(256) bf16 g_wff2_h[W_FF2_N],   g_wff2_l[W_FF2_N];
__device__ __align__(256) bf16 g_wout_h[W_OUT_N],   g_wout_l[W_OUT_N];

// ---------------- helpers ----------------
__device__ __forceinline__ uint32_t smem_u32(const void* p) {
    uint32_t a;
    asm("{ .reg .u64 t; cvta.to.shared.u64 t, %1; cvt.u32.u64 %0, t; }" : "=r"(a) : "l"(p));
    return a;
}
#define CPA16(dst, src) \
    asm volatile("cp.async.cg.shared.global [%0], [%1], 16;" :: "r"(dst), "l"(src))

__device__ __forceinline__ void split2(float x, bf16& h, bf16& l) {
    h = __float2bfloat16(x);
    l = __float2bfloat16(x - __bfloat162float(h));
}
__device__ __forceinline__ uint32_t packsplit(float x, float y, uint32_t& lo) {
    bf16 hx, lx, hy, ly;
    split2(x, hx, lx); split2(y, hy, ly);
    lo = ((uint32_t)__bfloat16_as_ushort(ly) << 16) | __bfloat16_as_ushort(lx);
    return ((uint32_t)__bfloat16_as_ushort(hy) << 16) | __bfloat16_as_ushort(hx);
}
__device__ __forceinline__ void lm4(uint32_t addr, uint32_t* r) {
    asm volatile("ldmatrix.sync.aligned.m8n8.x4.shared.b16 {%0,%1,%2,%3}, [%4];"
        : "=r"(r[0]), "=r"(r[1]), "=r"(r[2]), "=r"(r[3]) : "r"(addr));
}
__device__ __forceinline__ void lm2(uint32_t addr, uint32_t* r) {
    asm volatile("ldmatrix.sync.aligned.m8n8.x2.shared.b16 {%0,%1}, [%2];"
        : "=r"(r[0]), "=r"(r[1]) : "r"(addr));
}
__device__ __forceinline__ void lm2t(uint32_t addr, uint32_t* r) {
    asm volatile("ldmatrix.sync.aligned.m8n8.x2.trans.shared.b16 {%0,%1}, [%2];"
        : "=r"(r[0]), "=r"(r[1]) : "r"(addr));
}
__device__ __forceinline__ void MMA(float* d, const uint32_t* a, const uint32_t* b) {
    asm volatile("mma.sync.aligned.m16n8k16.row.col.f32.bf16.bf16.f32 "
        "{%0,%1,%2,%3}, {%4,%5,%6,%7}, {%8,%9}, {%0,%1,%2,%3};"
        : "+f"(d[0]), "+f"(d[1]), "+f"(d[2]), "+f"(d[3])
        : "r"(a[0]), "r"(a[1]), "r"(a[2]), "r"(a[3]), "r"(b[0]), "r"(b[1]));
}

// ============ HMMA split-bf16 GEMM (3-term) ============
// mode 0: +bias->f32  1: relu(+bias)->split  2: +bias+resid->f32  3: +bias->split
// mode 4: epilogue (rnorm[row]+cnorm[col]) - 2*acc -> f32 (rnorm via resid, cnorm via bias)
#define GM_STAGE 40960
#define GM_SMEM  (GM_STAGE * 2)

__global__ void __launch_bounds__(256, 1) gemm_mma(
    const bf16* __restrict__ Ahi, const bf16* __restrict__ Alo,
    const bf16* __restrict__ Whi, const bf16* __restrict__ Wlo,
    const float* __restrict__ bias, const float* __restrict__ resid, int ldr,
    float* __restrict__ C, bf16* __restrict__ Chi, bf16* __restrict__ Clo,
    int ldc, int K, int mode)
{
    extern __shared__ char smem[];
    const int tid = threadIdx.x, wid = tid >> 5, lane = tid & 31;
    const int bm = blockIdx.y * 128, bn = blockIdx.x * 128;
    const int wm = (wid & 1) * 64, wn = (wid >> 1) * 32;
    uint32_t sbase = smem_u32(smem);

    auto load_stage = [&](int s, int b) {
        uint32_t buf = sbase + b * GM_STAGE;
        #pragma unroll
        for (int i = 0; i < 8; i++) {
            int c = tid + i * 256;
            int tilei = c >> 9;
            int idx = c & 511;
            int row = idx >> 2, kch = (idx & 3) * 8;
            const bf16* src = (tilei == 0 ? Ahi : tilei == 1 ? Alo : tilei == 2 ? Whi : Wlo)
                + (size_t)((tilei < 2 ? bm : bn) + row) * K + s * 32 + kch;
            CPA16(buf + tilei * 10240 + row * 80 + kch * 2, src);
        }
        asm volatile("cp.async.commit_group;");
    };

    float acc[4][4][4];
    #pragma unroll
    for (int i = 0; i < 4; i++)
        #pragma unroll
        for (int j = 0; j < 4; j++)
            #pragma unroll
            for (int q = 0; q < 4; q++) acc[i][j][q] = 0.f;

    const int S = K >> 5;
    load_stage(0, 0);
    load_stage(1, 1);

    for (int s = 0; s < S; s++) {
        int b = s & 1;
        if (s >= S - 1) asm volatile("cp.async.wait_group 0;");
        else            asm volatile("cp.async.wait_group 1;");
        __syncthreads();
        uint32_t buf = sbase + b * GM_STAGE;
        #pragma unroll
        for (int ks = 0; ks < 2; ks++) {
            int k0 = ks * 16;
            uint32_t ah[4][4], al[4][4], bh[4][2], bl[4][2];
            int arow = wm + (lane & 15);
            int acol = (k0 + ((lane >> 4) & 1) * 8) * 2;
            #pragma unroll
            for (int mf = 0; mf < 4; mf++) {
                lm4(buf +         (arow + mf * 16) * 80 + acol, ah[mf]);
                lm4(buf + 10240 + (arow + mf * 16) * 80 + acol, al[mf]);
            }
            int l16 = lane & 15;
            int brow = wn + (l16 & 7);
            int bcol = (k0 + ((l16 >> 3) & 1) * 8) * 2;
            #pragma unroll
            for (int nf = 0; nf < 4; nf++) {
                lm2(buf + 20480 + (brow + nf * 8) * 80 + bcol, bh[nf]);
                lm2(buf + 30720 + (brow + nf * 8) * 80 + bcol, bl[nf]);
            }
            #pragma unroll
            for (int mf = 0; mf < 4; mf++)
                #pragma unroll
                for (int nf = 0; nf < 4; nf++) {
                    MMA(acc[mf][nf], ah[mf], bh[nf]);
                    MMA(acc[mf][nf], ah[mf], bl[nf]);
                    MMA(acc[mf][nf], al[mf], bh[nf]);
                }
        }
        __syncthreads();
        if (s + 2 < S) load_stage(s + 2, b);
    }

    #pragma unroll
    for (int mf = 0; mf < 4; mf++)
        #pragma unroll
        for (int nf = 0; nf < 4; nf++)
            #pragma unroll
            for (int half = 0; half < 2; half++) {
                int row = bm + wm + mf * 16 + (lane >> 2) + half * 8;
                int col = bn + wn + nf * 8 + 2 * (lane & 3);
                float2 v = make_float2(acc[mf][nf][half * 2], acc[mf][nf][half * 2 + 1]);
                size_t gr = (size_t)row;
                if (mode == 4) {
                    float xn = resid[gr];
                    float2 cn = *(const float2*)(bias + col);
                    v.x = (xn + cn.x) - 2.f * v.x;
                    v.y = (xn + cn.y) - 2.f * v.y;
                    *(float2*)(C + gr * ldc + col) = v;
                    continue;
                }
                float2 bv = *(const float2*)(bias + col);
                v.x += bv.x; v.y += bv.y;
                if (mode == 2) {
                    float2 r = *(const float2*)(resid + gr * ldr + col);
                    v.x += r.x; v.y += r.y;
                }
                if (mode == 1 || mode == 3) {
                    if (mode == 1) { v.x = fmaxf(v.x, 0.f); v.y = fmaxf(v.y, 0.f); }
                    uint32_t lo, hi = packsplit(v.x, v.y, lo);
                    *(uint32_t*)(Chi + gr * ldc + col) = hi;
                    *(uint32_t*)(Clo + gr * ldc + col) = lo;
                } else {
                    *(float2*)(C + gr * ldc + col) = v;
                }
            }
}

// ============ fused flash attention (split-bf16 HMMA) ============
#define FA_QBY (128 * 104 * 2)
#define FA_KBY (64 * 104 * 2)
#define FA_STAGE (4 * FA_KBY)
#define FA_SMEM (2 * FA_QBY + 2 * FA_STAGE)

__global__ void __launch_bounds__(256, 1) flash_attn(int causal) {
    extern __shared__ char sm_[];
    const int tid = threadIdx.x, wid = tid >> 5, lane = tid & 31;
    const int qt = blockIdx.x, bh = blockIdx.y;
    const int b = bh >> 3, h = bh & 7;
    uint32_t sb = smem_u32(sm_);
    uint32_t sQh = sb, sQl = sb + FA_QBY;
    auto stK = [&](int st, int arr) { return sb + 2*FA_QBY + st*FA_STAGE + arr*FA_KBY; };
    const size_t rowb = (size_t)(b * Ss);

    #pragma unroll
    for (int i = 0; i < 12; i++) {
        int c = tid + i * 256;
        int split = (c >= 1536) ? 1 : 0;
        int idx = c - split * 1536;
        int row = idx / 12, ch = idx % 12;
        const bf16* src = (split ? g_qkvl : g_qkvh) + (rowb + qt*128 + row)*(3*Dd) + h*DH + ch*8;
        CPA16((split ? sQl : sQh) + row*208 + ch*16, src);
    }
    asm volatile("cp.async.commit_group;");

    auto loadKV = [&](int kt, int st) {
        #pragma unroll
        for (int i = 0; i < 12; i++) {
            int c = tid + i * 256;
            int arr = c / 768, idx = c % 768;
            int row = idx / 12, ch = idx % 12;
            const bf16* base = (arr & 1) ? g_qkvl : g_qkvh;
            int off = (arr < 2) ? Dd : 2 * Dd;
            CPA16(stK(st, arr) + row*208 + ch*16,
                  base + (rowb + kt*64 + row)*(3*Dd) + off + h*DH + ch*8);
        }
        asm volatile("cp.async.commit_group;");
    };
    loadKV(0, 0);
    loadKV(1, 1);
    asm volatile("cp.async.wait_group 1;");
    __syncthreads();

    uint32_t qAh[6][4], qAl[6][4];
    {
        int arow = wid*16 + (lane & 15);
        #pragma unroll
        for (int j = 0; j < 6; j++) {
            int acol = (j*16 + ((lane >> 4) & 1) * 8) * 2;
            lm4(sQh + arow*208 + acol, qAh[j]);
            lm4(sQl + arow*208 + acol, qAl[j]);
        }
    }

    float O[12][4];
    #pragma unroll
    for (int nv = 0; nv < 12; nv++)
        #pragma unroll
        for (int q = 0; q < 4; q++) O[nv][q] = 0.f;
    float m0 = -3.4e38f, m1 = -3.4e38f, l0 = 0.f, l1 = 0.f;
    const int qr0 = qt*128 + wid*16 + (lane >> 2);
    const int l16 = lane & 15;
    const float isc = 0.10206207261596577f;

    for (int kt = 0; kt < 8; kt++) {
        int st = kt & 1;
        if (kt >= 7) asm volatile("cp.async.wait_group 0;");
        else         asm volatile("cp.async.wait_group 1;");
        __syncthreads();

        float S[8][4];
        #pragma unroll
        for (int nt = 0; nt < 8; nt++) { S[nt][0]=S[nt][1]=S[nt][2]=S[nt][3]=0.f; }
        uint32_t kb0 = stK(st, 0), kb1 = stK(st, 1);
        #pragma unroll
        for (int nt = 0; nt < 8; nt++) {
            uint32_t ba = (uint32_t)((nt*8 + (l16 & 7))*208 + (l16 >> 3)*16);
            #pragma unroll
            for (int j = 0; j < 6; j++) {
                uint32_t bhf[2], blf[2];
                lm2(kb0 + ba + j*32, bhf);
                lm2(kb1 + ba + j*32, blf);
                MMA(S[nt], qAh[j], bhf);
                MMA(S[nt], qAh[j], blf);
                MMA(S[nt], qAl[j], bhf);
            }
        }
        float mx0 = -3.4e38f, mx1 = -3.4e38f;
        #pragma unroll
        for (int nt = 0; nt < 8; nt++) {
            int k0 = kt*64 + nt*8 + 2*(lane & 3);
            float pd0 = g_padf[b*Ss + k0], pd1 = g_padf[b*Ss + k0 + 1];
            float s0 = S[nt][0]*isc + pd0 + ((causal && qr0 > k0)     ? NEGB : 0.f);
            float s1 = S[nt][1]*isc + pd1 + ((causal && qr0 > k0 + 1) ? NEGB : 0.f);
            float s2 = S[nt][2]*isc + pd0 + ((causal && qr0+8 > k0)   ? NEGB : 0.f);
            float s3 = S[nt][3]*isc + pd1 + ((causal && qr0+8 > k0+1) ? NEGB : 0.f);
            S[nt][0]=s0; S[nt][1]=s1; S[nt][2]=s2; S[nt][3]=s3;
            mx0 = fmaxf(mx0, fmaxf(s0, s1));
            mx1 = fmaxf(mx1, fmaxf(s2, s3));
        }
        mx0 = fmaxf(mx0, __shfl_xor_sync(0xffffffffu, mx0, 1));
        mx0 = fmaxf(mx0, __shfl_xor_sync(0xffffffffu, mx0, 2));
        mx1 = fmaxf(mx1, __shfl_xor_sync(0xffffffffu, mx1, 1));
        mx1 = fmaxf(mx1, __shfl_xor_sync(0xffffffffu, mx1, 2));
        float mn0 = fmaxf(m0, mx0), mn1 = fmaxf(m1, mx1);
        float cr0 = __expf(m0 - mn0), cr1 = __expf(m1 - mn1);
        m0 = mn0; m1 = mn1;
        l0 *= cr0; l1 *= cr1;
        #pragma unroll
        for (int nv = 0; nv < 12; nv++) {
            O[nv][0] *= cr0; O[nv][1] *= cr0; O[nv][2] *= cr1; O[nv][3] *= cr1;
        }
        #pragma unroll
        for (int nt = 0; nt < 8; nt++) {
            S[nt][0] = __expf(S[nt][0] - mn0); S[nt][1] = __expf(S[nt][1] - mn0);
            S[nt][2] = __expf(S[nt][2] - mn1); S[nt][3] = __expf(S[nt][3] - mn1);
            l0 += S[nt][0] + S[nt][1];
            l1 += S[nt][2] + S[nt][3];
        }
        uint32_t pAh[4][4], pAl[4][4];
        #pragma unroll
        for (int js = 0; js < 4; js++) {
            int a = 2*js, c = 2*js + 1;
            pAh[js][0] = packsplit(S[a][0], S[a][1], pAl[js][0]);
            pAh[js][1] = packsplit(S[a][2], S[a][3], pAl[js][1]);
            pAh[js][2] = packsplit(S[c][0], S[c][1], pAl[js][2]);
            pAh[js][3] = packsplit(S[c][2], S[c][3], pAl[js][3]);
        }
        uint32_t vb0 = stK(st, 2), vb1 = stK(st, 3);
        #pragma unroll
        for (int nv = 0; nv < 12; nv++) {
            #pragma unroll
            for (int js = 0; js < 4; js++) {
                uint32_t bhf[2], blf[2];
                uint32_t va = (uint32_t)((js*16 + l16)*208 + nv*16);
                lm2t(vb0 + va, bhf);
                lm2t(vb1 + va, blf);
                MMA(O[nv], pAh[js], bhf);
                MMA(O[nv], pAh[js], blf);
                MMA(O[nv], pAl[js], bhf);
            }
        }
        __syncthreads();
        if (kt + 2 < 8) loadKV(kt + 2, st);
    }

    l0 += __shfl_xor_sync(0xffffffffu, l0, 1);
    l0 += __shfl_xor_sync(0xffffffffu, l0, 2);
    l1 += __shfl_xor_sync(0xffffffffu, l1, 1);
    l1 += __shfl_xor_sync(0xffffffffu, l1, 2);
    float i0 = 1.f / l0, i1 = 1.f / l1;
    size_t gr0 = rowb + (size_t)qr0;
    size_t gr1 = gr0 + 8;
    int colb = h*DH + 2*(lane & 3);
    #pragma unroll
    for (int nv = 0; nv < 12; nv++) {
        uint32_t lo, hi;
        hi = packsplit(O[nv][0]*i0, O[nv][1]*i0, lo);
        *(uint32_t*)(g_att_h + gr0*Dd + colb + nv*8) = hi;
        *(uint32_t*)(g_att_l + gr0*Dd + colb + nv*8) = lo;
        hi = packsplit(O[nv][2]*i1, O[nv][3]*i1, lo);
        *(uint32_t*)(g_att_h + gr1*Dd + colb + nv*8) = hi;
        *(uint32_t*)(g_att_l + gr1*Dd + colb + nv*8) = lo;
    }
}

// ---------------- reductions ----------------
__device__ __forceinline__ float bsum(float v, float* sb) {
    int tid = threadIdx.x;
    #pragma unroll
    for (int o = 16; o > 0; o >>= 1) v += __shfl_down_sync(0xffffffffu, v, o);
    if ((tid & 31) == 0) sb[tid >> 5] = v;
    __syncthreads();
    float s = 0.f;
    if (tid < 32) {
        s = (tid < (int)(blockDim.x >> 5)) ? sb[tid] : 0.f;
        #pragma unroll
        for (int o = 16; o > 0; o >>= 1) s += __shfl_down_sync(0xffffffffu, s, o);
        if (tid == 0) sb[0] = s;
    }
    __syncthreads();
    float r = sb[0]; __syncthreads(); return r;
}

// ---------------- small kernels ----------------
__global__ void __launch_bounds__(256) cvt_split(const float* __restrict__ x,
                                                 bf16* __restrict__ hi, bf16* __restrict__ lo, int n4) {
    int i = blockIdx.x * 256 + threadIdx.x;
    if (i >= n4) return;
    float4 v = ((const float4*)x)[i];
    uint32_t l01, h01 = packsplit(v.x, v.y, l01);
    uint32_t l23, h23 = packsplit(v.z, v.w, l23);
    ((uint2*)hi)[i] = make_uint2(h01, h23);
    ((uint2*)lo)[i] = make_uint2(l01, l23);
}

__global__ void __launch_bounds__(256) rowstat_x(const float* __restrict__ x) {
    __shared__ float sb[32];
    int row = blockIdx.x, tid = threadIdx.x;
    float v[3];
    #pragma unroll
    for (int i = 0; i < 3; i++) v[i] = x[(size_t)row * Dd + tid + i * 256];
    float ss = bsum(v[0]*v[0] + v[1]*v[1] + v[2]*v[2], sb);
    int pad = (sqrtf(ss) <= 1e-6f) ? 1 : 0;
    if (tid == 0) { g_pad[row] = pad; g_xnorm[row] = pad ? 0.f : ss; g_padf[row] = pad ? NEGB : 0.f; }
    #pragma unroll
    for (int i = 0; i < 3; i++) {
        int c = tid + i * 256;
        float o = pad ? 0.f : v[i];
        g_mem[(size_t)row * Dd + c] = o;
        bf16 hh, ll; split2(o, hh, ll);
        g_mem_h[(size_t)row * Dd + c] = hh;
        g_mem_l[(size_t)row * Dd + c] = ll;
    }
}
__global__ void __launch_bounds__(256) rowstat_cb(const float* __restrict__ cb) {
    __shared__ float sb[32];
    int row = blockIdx.x, tid = threadIdx.x;
    float ss = 0.f;
    #pragma unroll
    for (int i = 0; i < 3; i++) { float v = cb[(size_t)row * Dd + tid + i * 256]; ss += v * v; }
    ss = bsum(ss, sb);
    if (tid == 0) g_cnorm[row] = ss;
}

// ---------------- layernorm (+split) ----------------
__global__ void __launch_bounds__(256) layernorm(const float* __restrict__ gam,
                                                 const float* __restrict__ bet) {
    __shared__ float sb[32];
    int row = blockIdx.x, tid = threadIdx.x;
    const float* x = g_tmp + (size_t)row * Dd;
    float v[3];
    #pragma unroll
    for (int i = 0; i < 3; i++) v[i] = x[tid + i * 256];
    float s = bsum(v[0] + v[1] + v[2], sb);
    float mean = s / 768.0f;
    float d2 = 0.f;
    #pragma unroll
    for (int i = 0; i < 3; i++) { float d = v[i] - mean; d2 += d * d; }
    d2 = bsum(d2, sb);
    float inv = 1.0f / sqrtf(d2 / 768.0f + 1e-5f);
    #pragma unroll
    for (int i = 0; i < 3; i++) {
        int c = tid + i * 256;
        float o = (v[i] - mean) * inv * gam[c] + bet[c];
        g_h[(size_t)row * Dd + c] = o;
        bf16 hh, ll; split2(o, hh, ll);
        g_h_h[(size_t)row * Dd + c] = hh;
        g_h_l[(size_t)row * Dd + c] = ll;
    }
}

// ---------------- threefry (JAX-exact) ----------------
__device__ __forceinline__ uint32_t rotl32(uint32_t x, int d) { return (x << d) | (x >> (32 - d)); }
__device__ void threefry2x32(uint32_t k0, uint32_t k1, uint32_t x0, uint32_t x1,
                             uint32_t& o0, uint32_t& o1) {
    uint32_t k2 = k0 ^ k1 ^ 0x1BD11BDAu;
    x0 += k0; x1 += k1;
    x0+=x1; x1=rotl32(x1,13); x1^=x0;  x0+=x1; x1=rotl32(x1,15); x1^=x0;
    x0+=x1; x1=rotl32(x1,26); x1^=x0;  x0+=x1; x1=rotl32(x1,6);  x1^=x0;
    x0 += k1; x1 += k2 + 1u;
    x0+=x1; x1=rotl32(x1,17); x1^=x0;  x0+=x1; x1=rotl32(x1,29); x1^=x0;
    x0+=x1; x1=rotl32(x1,16); x1^=x0;  x0+=x1; x1=rotl32(x1,24); x1^=x0;
    x0 += k2; x1 += k0 + 2u;
    x0+=x1; x1=rotl32(x1,13); x1^=x0;  x0+=x1; x1=rotl32(x1,15); x1^=x0;
    x0+=x1; x1=rotl32(x1,26); x1^=x0;  x0+=x1; x1=rotl32(x1,6);  x1^=x0;
    x0 += k0; x1 += k1 + 3u;
    x0+=x1; x1=rotl32(x1,17); x1^=x0;  x0+=x1; x1=rotl32(x1,29); x1^=x0;
    x0+=x1; x1=rotl32(x1,16); x1^=x0;  x0+=x1; x1=rotl32(x1,24); x1^=x0;
    x0 += k1; x1 += k2 + 4u;
    x0+=x1; x1=rotl32(x1,13); x1^=x0;  x0+=x1; x1=rotl32(x1,15); x1^=x0;
    x0+=x1; x1=rotl32(x1,26); x1^=x0;  x0+=x1; x1=rotl32(x1,6);  x1^=x0;
    x0 += k2; x1 += k0 + 5u;
    o0 = x0; o1 = x1;
}

// ---------------- VQ: approx top-16 -> exact fp32 rescore -> top-10 gumbel ----------------
__global__ void __launch_bounds__(256) vq_topk_refine(const float* __restrict__ cbf) {
    int row = blockIdx.x, tid = threadIdx.x;
    const float* __restrict__ drow = g_dist + (size_t)row * Kc;
    float td[16]; int ti[16];
    #pragma unroll
    for (int j = 0; j < 16; j++) { td[j] = 3.4e38f; ti[j] = 0x7fffffff; }
    for (int c = tid; c < Kc; c += 256) {
        float v = drow[c];
        if (v < td[15] || (v == td[15] && c < ti[15])) {
            int pos = 15;
            #pragma unroll
            for (int j = 14; j >= 0; j--) {
                bool lt = (v < td[j]) || (v == td[j] && c < ti[j]);
                if (lt) pos = j;
            }
            #pragma unroll
            for (int j = 15; j > 0; j--)
                if (j > pos) { td[j] = td[j-1]; ti[j] = ti[j-1]; }
            td[pos] = v; ti[pos] = c;
        }
    }
    __shared__ float sd[4096];
    __shared__ int   si[4096];
    __shared__ float ex[16];
    #pragma unroll
    for (int j = 0; j < 16; j++) { sd[tid*16+j] = td[j]; si[tid*16+j] = ti[j]; }
    for (int stride = 128; stride >= 1; stride >>= 1) {
        __syncthreads();
        if (tid < stride) {
            float od[16]; int oi[16];
            int a = 0, b2 = 0;
            #pragma unroll
            for (int j = 0; j < 16; j++) {
                float da = sd[tid*16+a], db = sd[(tid+stride)*16+b2];
                int   ia = si[tid*16+a], ib = si[(tid+stride)*16+b2];
                bool ta = (da < db) || (da == db && ia <= ib);
                if (ta) { od[j]=da; oi[j]=ia; a++; } else { od[j]=db; oi[j]=ib; b2++; }
            }
            #pragma unroll
            for (int j = 0; j < 16; j++) { sd[tid*16+j]=od[j]; si[tid*16+j]=oi[j]; }
        }
    }
    __syncthreads();
    // exact fp32 rescore of the 16 candidates (8 warps x 2)
    int wid = tid >> 5, lane = tid & 31;
    const float* xr = g_mem + (size_t)row * Dd;
    for (int t = wid; t < 16; t += 8) {
        int ci = si[t];
        const float* cr = cbf + (size_t)ci * Dd;
        float s = 0.f;
        #pragma unroll
        for (int e = 0; e < 24; e++) s = fmaf(xr[lane + e*32], cr[lane + e*32], s);
        #pragma unroll
        for (int o = 16; o > 0; o >>= 1) s += __shfl_down_sync(0xffffffffu, s, o);
        if (lane == 0) ex[t] = (g_xnorm[row] + g_cnorm[ci]) - 2.f * s;
    }
    __syncthreads();
    if (tid == 0) {
        float dd[16]; int ii[16];
        #pragma unroll
        for (int j = 0; j < 16; j++) { dd[j] = ex[j]; ii[j] = si[j]; }
        #pragma unroll
        for (int a = 0; a < 10; a++) {
            int best = a;
            #pragma unroll
            for (int b2 = 0; b2 < 16; b2++) {
                if (b2 <= a) continue;
                bool lt = (dd[b2] < dd[best]) || (dd[b2] == dd[best] && ii[b2] < ii[best]);
                if (lt) best = b2;
            }
            float tdv = dd[a]; dd[a] = dd[best]; dd[best] = tdv;
            int tiv = ii[a]; ii[a] = ii[best]; ii[best] = tiv;
        }
        float bestv = -3.4e38f;
        int bi = ii[0];
        for (int j = 0; j < 10; j++) {
            uint32_t e = (uint32_t)(row * 10 + j);
            uint32_t o0, o1;
            threefry2x32(0u, 42u, 0u, e, o0, o1);
            uint32_t bits = o0 ^ o1;
            float u = __uint_as_float((bits >> 9) | 0x3f800000u) - 1.0f;
            u = fmaxf(1e-10f, u + 1e-10f);
            float gmb = -logf(-logf(u));
            float sc = -dd[j] + gmb;
            if (sc > bestv) { bestv = sc; bi = ii[j]; }
        }
        g_enc[row] = bi;
    }
}

__global__ void __launch_bounds__(256) vq_quantize(const float* __restrict__ cb) {
    int row = blockIdx.x, tid = threadIdx.x;
    int e = g_enc[row];
    #pragma unroll
    for (int i = 0; i < 3; i++) {
        int c = tid + i * 256;
        float z = g_mem[(size_t)row * Dd + c];
        float q = cb[(size_t)e * Dd + c];
        float o = z + (q - z);
        g_h[(size_t)row * Dd + c] = o;
        bf16 hh, ll; split2(o, hh, ll);
        g_h_h[(size_t)row * Dd + c] = hh;
        g_h_l[(size_t)row * Dd + c] = ll;
    }
}

// ---------------- host ----------------
static void* sym(const void* s) { void* p = nullptr; cudaGetSymbolAddress(&p, s); return p; }

extern "C" void kernel_launch(void* const* d_in, const int* in_sizes, int n_in,
                              void* d_out, int out_size) {
    const float* x     = (const float*)d_in[0];
    const float* cb    = (const float*)d_in[1];
    const float* sib   = (const float*)d_in[3];
    const float* sob   = (const float*)d_in[5];
    const float* cib   = (const float*)d_in[7];
    const float* cob   = (const float*)d_in[9];
    const float* ln1g  = (const float*)d_in[10];
    const float* ln1b  = (const float*)d_in[11];
    const float* ln2g  = (const float*)d_in[12];
    const float* ln2b  = (const float*)d_in[13];
    const float* ln3g  = (const float*)d_in[14];
    const float* ln3b  = (const float*)d_in[15];
    const float* fb1   = (const float*)d_in[17];
    const float* fb2   = (const float*)d_in[19];
    const float* outb  = (const float*)d_in[21];
    float* outp = (float*)d_out;

    cudaFuncSetAttribute(gemm_mma, cudaFuncAttributeMaxDynamicSharedMemorySize, GM_SMEM);
    cudaFuncSetAttribute(flash_attn, cudaFuncAttributeMaxDynamicSharedMemorySize, FA_SMEM);

    float* p_mem  = (float*)sym(g_mem);
    float* p_h    = (float*)sym(g_h);
    float* p_tmp  = (float*)sym(g_tmp);
    float* p_dist = (float*)sym(g_dist);
    float* p_xn   = (float*)sym(g_xnorm);
    float* p_cn   = (float*)sym(g_cnorm);
    bf16 *qkh = (bf16*)sym(g_qkvh), *qkl = (bf16*)sym(g_qkvl);
    bf16 *hh = (bf16*)sym(g_h_h),   *hl = (bf16*)sym(g_h_l);
    bf16 *ah = (bf16*)sym(g_att_h), *al = (bf16*)sym(g_att_l);
    bf16 *mh = (bf16*)sym(g_mem_h), *ml = (bf16*)sym(g_mem_l);
    bf16 *cbh = (bf16*)sym(g_cb_h), *cbl = (bf16*)sym(g_cb_l);
    bf16 *fh = (bf16*)sym(g_ff_h),  *fl = (bf16*)sym(g_ff_l);
    bf16 *wsa_h = (bf16*)sym(g_wsain_h),  *wsa_l = (bf16*)sym(g_wsain_l);
    bf16 *wso_h = (bf16*)sym(g_wsaout_h), *wso_l = (bf16*)sym(g_wsaout_l);
    bf16 *wca_h = (bf16*)sym(g_wcain_h),  *wca_l = (bf16*)sym(g_wcain_l);
    bf16 *wco_h = (bf16*)sym(g_wcaout_h), *wco_l = (bf16*)sym(g_wcaout_l);
    bf16 *wf1_h = (bf16*)sym(g_wff1_h),   *wf1_l = (bf16*)sym(g_wff1_l);
    bf16 *wf2_h = (bf16*)sym(g_wff2_h),   *wf2_l = (bf16*)sym(g_wff2_l);
    bf16 *wo_h  = (bf16*)sym(g_wout_h),   *wo_l  = (bf16*)sym(g_wout_l);

    auto CVT = [](const float* s, bf16* h, bf16* l, size_t n) {
        int n4 = (int)(n / 4);
        cvt_split<<<(n4 + 255) / 256, 256>>>(s, h, l, n4);
    };
    auto TG = [&](const bf16* Ah, const bf16* Al, const bf16* Wh, const bf16* Wl,
                  const float* bias, const float* resid, float* C, bf16* Ch, bf16* Cl,
                  int ldc, int N, int K, int mode) {
        dim3 grid(N / 128, NTOK / 128);
        gemm_mma<<<grid, 256, GM_SMEM>>>(Ah, Al, Wh, Wl, bias, resid, Dd, C, Ch, Cl, ldc, K, mode);
    };

    CVT((const float*)d_in[2],  wsa_h, wsa_l, (size_t)W_SAIN_N);
    CVT((const float*)d_in[4],  wso_h, wso_l, (size_t)W_SQ_N);
    CVT((const float*)d_in[6],  wca_h, wca_l, (size_t)W_SAIN_N);
    CVT((const float*)d_in[8],  wco_h, wco_l, (size_t)W_SQ_N);
    CVT((const float*)d_in[16], wf1_h, wf1_l, (size_t)W_FF1_N);
    CVT((const float*)d_in[18], wf2_h, wf2_l, (size_t)W_FF2_N);
    CVT((const float*)d_in[20], wo_h,  wo_l,  (size_t)W_OUT_N);
    CVT(cb, cbh, cbl, (size_t)Kc * Dd);

    // VQ: approx distances via 3-term HMMA, then exact fp32 rescore of top-16
    rowstat_x<<<NTOK, 256>>>(x);
    rowstat_cb<<<Kc, 256>>>(cb);
    TG(mh, ml, cbh, cbl, p_cn, p_xn, p_dist, nullptr, nullptr, Kc, Kc, Dd, 4);
    vq_topk_refine<<<NTOK, 256>>>(cb);
    vq_quantize<<<NTOK, 256>>>(cb);

    for (int l = 0; l < Ll; l++) {
        size_t win = (size_t)l * 3 * Dd * Dd, wsq = (size_t)l * Dd * Dd;
        // self-attention
        TG(hh, hl, wsa_h + win, wsa_l + win, sib + (size_t)l*3*Dd, nullptr,
           nullptr, qkh, qkl, 3*Dd, 3*Dd, Dd, 3);
        flash_attn<<<dim3(4, Bb*Hh), 256, FA_SMEM>>>(1);
        TG(ah, al, wso_h + wsq, wso_l + wsq, sob + (size_t)l*Dd, p_h,
           p_tmp, nullptr, nullptr, Dd, Dd, Dd, 2);
        layernorm<<<NTOK, 256>>>(ln1g + (size_t)l*Dd, ln1b + (size_t)l*Dd);

        // cross-attention
        TG(hh, hl, wca_h + win, wca_l + win, cib + (size_t)l*3*Dd, nullptr,
           nullptr, qkh, qkl, 3*Dd, Dd, Dd, 3);
        TG(mh, ml, wca_h + win + (size_t)Dd*Dd, wca_l + win + (size_t)Dd*Dd,
           cib + (size_t)l*3*Dd + Dd, nullptr,
           nullptr, qkh + Dd, qkl + Dd, 3*Dd, 2*Dd, Dd, 3);
        flash_attn<<<dim3(4, Bb*Hh), 256, FA_SMEM>>>(0);
        TG(ah, al, wco_h + wsq, wco_l + wsq, cob + (size_t)l*Dd, p_h,
           p_tmp, nullptr, nullptr, Dd, Dd, Dd, 2);
        layernorm<<<NTOK, 256>>>(ln2g + (size_t)l*Dd, ln2b + (size_t)l*Dd);

        // feed-forward
        TG(hh, hl, wf1_h + (size_t)l*FFd*Dd, wf1_l + (size_t)l*FFd*Dd,
           fb1 + (size_t)l*FFd, nullptr, nullptr, fh, fl, FFd, FFd, Dd, 1);
        TG(fh, fl, wf2_h + (size_t)l*Dd*FFd, wf2_l + (size_t)l*Dd*FFd,
           fb2 + (size_t)l*Dd, p_h, p_tmp, nullptr, nullptr, Dd, Dd, FFd, 2);
        layernorm<<<NTOK, 256>>>(ln3g + (size_t)l*Dd, ln3b + (size_t)l*Dd);
    }

    TG(hh, hl, wo_h, wo_l, outb, nullptr, outp, nullptr, nullptr, Dd, Dd, Dd, 0);
}

// round 16
// speedup vs baseline: 1.1035x; 1.1035x over previous
#include <cuda_runtime.h>
#include <cuda_bf16.h>
#include <cstdint>
#include <math.h>

#define Bb 16
#define Ss 512
#define Dd 768
#define Kc 8192
#define Hh 8
#define Ll 6
#define FFd 2048
#define NTOK 8192
#define DH 96
#define NEGB (-1e9f)
typedef __nv_bfloat16 bf16;

#define W_SAIN_N  (Ll * 3 * Dd * Dd)
#define W_SQ_N    (Ll * Dd * Dd)
#define W_FF1_N   (Ll * FFd * Dd)
#define W_FF2_N   (Ll * Dd * FFd)
#define W_OUT_N   (Dd * Dd)

// ---------------- scratch ----------------
__device__ __align__(256) float g_mem  [NTOK * Dd];
__device__ __align__(256) float g_h    [NTOK * Dd];
__device__ __align__(256) float g_tmp  [NTOK * Dd];
__device__ __align__(256) float g_dist [(size_t)NTOK * Kc];
__device__ float g_xnorm[NTOK];
__device__ float g_cnorm[Kc];
__device__ float g_padf [NTOK];
__device__ int   g_pad  [NTOK];
__device__ int   g_enc  [NTOK];

__device__ __align__(256) bf16 g_qkvh[NTOK*3*Dd], g_qkvl[NTOK*3*Dd];
__device__ __align__(256) bf16 g_h_h[NTOK*Dd],  g_h_l[NTOK*Dd];
__device__ __align__(256) bf16 g_att_h[NTOK*Dd],g_att_l[NTOK*Dd];
__device__ __align__(256) bf16 g_mem_h[NTOK*Dd],g_mem_l[NTOK*Dd];
__device__ __align__(256) bf16 g_cb_h[Kc*Dd],   g_cb_l[Kc*Dd];
__device__ __align__(256) bf16 g_ff_h[NTOK*FFd],g_ff_l[NTOK*FFd];
__device__ __align__(256) bf16 g_wsain_h[W_SAIN_N], g_wsain_l[W_SAIN_N];
__device__ __align__(256) bf16 g_wsaout_h[W_SQ_N],  g_wsaout_l[W_SQ_N];
__device__ __align__(256) bf16 g_wcain_h[W_SAIN_N], g_wcain_l[W_SAIN_N];
__device__ __align__(256) bf16 g_wcaout_h[W_SQ_N],  g_wcaout_l[W_SQ_N];
__device__ __align__(256) bf16 g_wff1_h[W_FF1_N],   g_wff1_l[W_FF1_N];
__device__ __align__(256) bf16 g_wff2_h[W_FF2_N],   g_wff2_l[W_FF2_N];
__device__ __align__(256) bf16 g_wout_h[W_OUT_N],   g_wout_l[W_OUT_N];

// ---------------- helpers ----------------
__device__ __forceinline__ uint32_t smem_u32(const void* p) {
    uint32_t a;
    asm("{ .reg .u64 t; cvta.to.shared.u64 t, %1; cvt.u32.u64 %0, t; }" : "=r"(a) : "l"(p));
    return a;
}
#define CPA16(dst, src) \
    asm volatile("cp.async.cg.shared.global [%0], [%1], 16;" :: "r"(dst), "l"(src))

__device__ __forceinline__ void split2(float x, bf16& h, bf16& l) {
    h = __float2bfloat16(x);
    l = __float2bfloat16(x - __bfloat162float(h));
}
__device__ __forceinline__ uint32_t packsplit(float x, float y, uint32_t& lo) {
    bf16 hx, lx, hy, ly;
    split2(x, hx, lx); split2(y, hy, ly);
    lo = ((uint32_t)__bfloat16_as_ushort(ly) << 16) | __bfloat16_as_ushort(lx);
    return ((uint32_t)__bfloat16_as_ushort(hy) << 16) | __bfloat16_as_ushort(hx);
}
__device__ __forceinline__ void lm4(uint32_t addr, uint32_t* r) {
    asm volatile("ldmatrix.sync.aligned.m8n8.x4.shared.b16 {%0,%1,%2,%3}, [%4];"
        : "=r"(r[0]), "=r"(r[1]), "=r"(r[2]), "=r"(r[3]) : "r"(addr));
}
__device__ __forceinline__ void lm2(uint32_t addr, uint32_t* r) {
    asm volatile("ldmatrix.sync.aligned.m8n8.x2.shared.b16 {%0,%1}, [%2];"
        : "=r"(r[0]), "=r"(r[1]) : "r"(addr));
}
__device__ __forceinline__ void lm2t(uint32_t addr, uint32_t* r) {
    asm volatile("ldmatrix.sync.aligned.m8n8.x2.trans.shared.b16 {%0,%1}, [%2];"
        : "=r"(r[0]), "=r"(r[1]) : "r"(addr));
}
__device__ __forceinline__ void MMA(float* d, const uint32_t* a, const uint32_t* b) {
    asm volatile("mma.sync.aligned.m16n8k16.row.col.f32.bf16.bf16.f32 "
        "{%0,%1,%2,%3}, {%4,%5,%6,%7}, {%8,%9}, {%0,%1,%2,%3};"
        : "+f"(d[0]), "+f"(d[1]), "+f"(d[2]), "+f"(d[3])
        : "r"(a[0]), "r"(a[1]), "r"(a[2]), "r"(a[3]), "r"(b[0]), "r"(b[1]));
}

// ============ HMMA split-bf16 GEMM, 128x256 tile ============
// mode 0: +bias->f32  1: relu(+bias)->split  2: +bias+resid->f32  3: +bias->split
// mode 4: epilogue (rnorm[row]+cnorm[col]) - 2*acc -> f32 (rnorm via resid, cnorm via bias)
// stage layout: Ah@0 (128x80B), Al@10240, Wh@20480 (256x80B), Wl@40960
#define GM_STAGE 61440
#define GM_SMEM  (GM_STAGE * 2)

__global__ void __launch_bounds__(256, 1) gemm_mma(
    const bf16* __restrict__ Ahi, const bf16* __restrict__ Alo,
    const bf16* __restrict__ Whi, const bf16* __restrict__ Wlo,
    const float* __restrict__ bias, const float* __restrict__ resid, int ldr,
    float* __restrict__ C, bf16* __restrict__ Chi, bf16* __restrict__ Clo,
    int ldc, int K, int mode)
{
    extern __shared__ char smem[];
    const int tid = threadIdx.x, wid = tid >> 5, lane = tid & 31;
    const int bm = blockIdx.y * 128, bn = blockIdx.x * 256;
    const int wm = (wid & 1) * 64, wn = (wid >> 1) * 64;
    uint32_t sbase = smem_u32(smem);

    auto load_stage = [&](int s, int b) {
        uint32_t buf = sbase + b * GM_STAGE;
        #pragma unroll
        for (int i = 0; i < 12; i++) {
            int c = tid + i * 256;
            const bf16* src; uint32_t toff; int row, kch;
            if (c < 1024) {
                int hi = (c < 512) ? 1 : 0;
                int idx = c & 511;
                row = idx >> 2; kch = (idx & 3) * 8;
                src = (hi ? Ahi : Alo) + (size_t)(bm + row) * K + s * 32 + kch;
                toff = hi ? 0u : 10240u;
            } else {
                int c2 = c - 1024;
                int hi = (c2 < 1024) ? 1 : 0;
                int idx = c2 & 1023;
                row = idx >> 2; kch = (idx & 3) * 8;
                src = (hi ? Whi : Wlo) + (size_t)(bn + row) * K + s * 32 + kch;
                toff = hi ? 20480u : 40960u;
            }
            CPA16(buf + toff + row * 80 + kch * 2, src);
        }
        asm volatile("cp.async.commit_group;");
    };

    float acc[4][8][4];
    #pragma unroll
    for (int i = 0; i < 4; i++)
        #pragma unroll
        for (int j = 0; j < 8; j++)
            #pragma unroll
            for (int q = 0; q < 4; q++) acc[i][j][q] = 0.f;

    const int S = K >> 5;
    load_stage(0, 0);
    load_stage(1, 1);

    for (int s = 0; s < S; s++) {
        int b = s & 1;
        if (s >= S - 1) asm volatile("cp.async.wait_group 0;");
        else            asm volatile("cp.async.wait_group 1;");
        __syncthreads();
        uint32_t buf = sbase + b * GM_STAGE;
        #pragma unroll
        for (int ks = 0; ks < 2; ks++) {
            int k0 = ks * 16;
            uint32_t ah[4][4], al[4][4];
            int arow = wm + (lane & 15);
            int acol = (k0 + ((lane >> 4) & 1) * 8) * 2;
            #pragma unroll
            for (int mf = 0; mf < 4; mf++) {
                lm4(buf +          (arow + mf * 16) * 80 + acol, ah[mf]);
                lm4(buf + 10240u + (arow + mf * 16) * 80 + acol, al[mf]);
            }
            int l16 = lane & 15;
            int brow = wn + (l16 & 7);
            int bcol = (k0 + ((l16 >> 3) & 1) * 8) * 2;
            #pragma unroll
            for (int nf = 0; nf < 8; nf++) {
                uint32_t bh[2], bl[2];
                lm2(buf + 20480u + (brow + nf * 8) * 80 + bcol, bh);
                lm2(buf + 40960u + (brow + nf * 8) * 80 + bcol, bl);
                #pragma unroll
                for (int mf = 0; mf < 4; mf++) {
                    MMA(acc[mf][nf], ah[mf], bh);
                    MMA(acc[mf][nf], ah[mf], bl);
                    MMA(acc[mf][nf], al[mf], bh);
                }
            }
        }
        __syncthreads();
        if (s + 2 < S) load_stage(s + 2, b);
    }

    #pragma unroll
    for (int mf = 0; mf < 4; mf++)
        #pragma unroll
        for (int nf = 0; nf < 8; nf++)
            #pragma unroll
            for (int half = 0; half < 2; half++) {
                int row = bm + wm + mf * 16 + (lane >> 2) + half * 8;
                int col = bn + wn + nf * 8 + 2 * (lane & 3);
                float2 v = make_float2(acc[mf][nf][half * 2], acc[mf][nf][half * 2 + 1]);
                size_t gr = (size_t)row;
                if (mode == 4) {
                    float xn = resid[gr];
                    float2 cn = *(const float2*)(bias + col);
                    v.x = (xn + cn.x) - 2.f * v.x;
                    v.y = (xn + cn.y) - 2.f * v.y;
                    *(float2*)(C + gr * ldc + col) = v;
                    continue;
                }
                float2 bv = *(const float2*)(bias + col);
                v.x += bv.x; v.y += bv.y;
                if (mode == 2) {
                    float2 r = *(const float2*)(resid + gr * ldr + col);
                    v.x += r.x; v.y += r.y;
                }
                if (mode == 1 || mode == 3) {
                    if (mode == 1) { v.x = fmaxf(v.x, 0.f); v.y = fmaxf(v.y, 0.f); }
                    uint32_t lo, hi = packsplit(v.x, v.y, lo);
                    *(uint32_t*)(Chi + gr * ldc + col) = hi;
                    *(uint32_t*)(Clo + gr * ldc + col) = lo;
                } else {
                    *(float2*)(C + gr * ldc + col) = v;
                }
            }
}

// ============ fused flash attention (split-bf16 HMMA) ============
#define FA_QBY (128 * 104 * 2)
#define FA_KBY (64 * 104 * 2)
#define FA_STAGE (4 * FA_KBY)
#define FA_SMEM (2 * FA_QBY + 2 * FA_STAGE)

__global__ void __launch_bounds__(256, 1) flash_attn(int causal) {
    extern __shared__ char sm_[];
    const int tid = threadIdx.x, wid = tid >> 5, lane = tid & 31;
    const int qt = blockIdx.x, bh = blockIdx.y;
    const int b = bh >> 3, h = bh & 7;
    uint32_t sb = smem_u32(sm_);
    uint32_t sQh = sb, sQl = sb + FA_QBY;
    auto stK = [&](int st, int arr) { return sb + 2*FA_QBY + st*FA_STAGE + arr*FA_KBY; };
    const size_t rowb = (size_t)(b * Ss);

    #pragma unroll
    for (int i = 0; i < 12; i++) {
        int c = tid + i * 256;
        int split = (c >= 1536) ? 1 : 0;
        int idx = c - split * 1536;
        int row = idx / 12, ch = idx % 12;
        const bf16* src = (split ? g_qkvl : g_qkvh) + (rowb + qt*128 + row)*(3*Dd) + h*DH + ch*8;
        CPA16((split ? sQl : sQh) + row*208 + ch*16, src);
    }
    asm volatile("cp.async.commit_group;");

    auto loadKV = [&](int kt, int st) {
        #pragma unroll
        for (int i = 0; i < 12; i++) {
            int c = tid + i * 256;
            int arr = c / 768, idx = c % 768;
            int row = idx / 12, ch = idx % 12;
            const bf16* base = (arr & 1) ? g_qkvl : g_qkvh;
            int off = (arr < 2) ? Dd : 2 * Dd;
            CPA16(stK(st, arr) + row*208 + ch*16,
                  base + (rowb + kt*64 + row)*(3*Dd) + off + h*DH + ch*8);
        }
        asm volatile("cp.async.commit_group;");
    };
    loadKV(0, 0);
    loadKV(1, 1);
    asm volatile("cp.async.wait_group 1;");
    __syncthreads();

    uint32_t qAh[6][4], qAl[6][4];
    {
        int arow = wid*16 + (lane & 15);
        #pragma unroll
        for (int j = 0; j < 6; j++) {
            int acol = (j*16 + ((lane >> 4) & 1) * 8) * 2;
            lm4(sQh + arow*208 + acol, qAh[j]);
            lm4(sQl + arow*208 + acol, qAl[j]);
        }
    }

    float O[12][4];
    #pragma unroll
    for (int nv = 0; nv < 12; nv++)
        #pragma unroll
        for (int q = 0; q < 4; q++) O[nv][q] = 0.f;
    float m0 = -3.4e38f, m1 = -3.4e38f, l0 = 0.f, l1 = 0.f;
    const int qr0 = qt*128 + wid*16 + (lane >> 2);
    const int l16 = lane & 15;
    const float isc = 0.10206207261596577f;

    for (int kt = 0; kt < 8; kt++) {
        int st = kt & 1;
        if (kt >= 7) asm volatile("cp.async.wait_group 0;");
        else         asm volatile("cp.async.wait_group 1;");
        __syncthreads();

        float S[8][4];
        #pragma unroll
        for (int nt = 0; nt < 8; nt++) { S[nt][0]=S[nt][1]=S[nt][2]=S[nt][3]=0.f; }
        uint32_t kb0 = stK(st, 0), kb1 = stK(st, 1);
        #pragma unroll
        for (int nt = 0; nt < 8; nt++) {
            uint32_t ba = (uint32_t)((nt*8 + (l16 & 7))*208 + (l16 >> 3)*16);
            #pragma unroll
            for (int j = 0; j < 6; j++) {
                uint32_t bhf[2], blf[2];
                lm2(kb0 + ba + j*32, bhf);
                lm2(kb1 + ba + j*32, blf);
                MMA(S[nt], qAh[j], bhf);
                MMA(S[nt], qAh[j], blf);
                MMA(S[nt], qAl[j], bhf);
            }
        }
        float mx0 = -3.4e38f, mx1 = -3.4e38f;
        #pragma unroll
        for (int nt = 0; nt < 8; nt++) {
            int k0 = kt*64 + nt*8 + 2*(lane & 3);
            float pd0 = g_padf[b*Ss + k0], pd1 = g_padf[b*Ss + k0 + 1];
            float s0 = S[nt][0]*isc + pd0 + ((causal && qr0 > k0)     ? NEGB : 0.f);
            float s1 = S[nt][1]*isc + pd1 + ((causal && qr0 > k0 + 1) ? NEGB : 0.f);
            float s2 = S[nt][2]*isc + pd0 + ((causal && qr0+8 > k0)   ? NEGB : 0.f);
            float s3 = S[nt][3]*isc + pd1 + ((causal && qr0+8 > k0+1) ? NEGB : 0.f);
            S[nt][0]=s0; S[nt][1]=s1; S[nt][2]=s2; S[nt][3]=s3;
            mx0 = fmaxf(mx0, fmaxf(s0, s1));
            mx1 = fmaxf(mx1, fmaxf(s2, s3));
        }
        mx0 = fmaxf(mx0, __shfl_xor_sync(0xffffffffu, mx0, 1));
        mx0 = fmaxf(mx0, __shfl_xor_sync(0xffffffffu, mx0, 2));
        mx1 = fmaxf(mx1, __shfl_xor_sync(0xffffffffu, mx1, 1));
        mx1 = fmaxf(mx1, __shfl_xor_sync(0xffffffffu, mx1, 2));
        float mn0 = fmaxf(m0, mx0), mn1 = fmaxf(m1, mx1);
        float cr0 = __expf(m0 - mn0), cr1 = __expf(m1 - mn1);
        m0 = mn0; m1 = mn1;
        l0 *= cr0; l1 *= cr1;
        #pragma unroll
        for (int nv = 0; nv < 12; nv++) {
            O[nv][0] *= cr0; O[nv][1] *= cr0; O[nv][2] *= cr1; O[nv][3] *= cr1;
        }
        #pragma unroll
        for (int nt = 0; nt < 8; nt++) {
            S[nt][0] = __expf(S[nt][0] - mn0); S[nt][1] = __expf(S[nt][1] - mn0);
            S[nt][2] = __expf(S[nt][2] - mn1); S[nt][3] = __expf(S[nt][3] - mn1);
            l0 += S[nt][0] + S[nt][1];
            l1 += S[nt][2] + S[nt][3];
        }
        uint32_t pAh[4][4], pAl[4][4];
        #pragma unroll
        for (int js = 0; js < 4; js++) {
            int a = 2*js, c = 2*js + 1;
            pAh[js][0] = packsplit(S[a][0], S[a][1], pAl[js][0]);
            pAh[js][1] = packsplit(S[a][2], S[a][3], pAl[js][1]);
            pAh[js][2] = packsplit(S[c][0], S[c][1], pAl[js][2]);
            pAh[js][3] = packsplit(S[c][2], S[c][3], pAl[js][3]);
        }
        uint32_t vb0 = stK(st, 2), vb1 = stK(st, 3);
        #pragma unroll
        for (int nv = 0; nv < 12; nv++) {
            #pragma unroll
            for (int js = 0; js < 4; js++) {
                uint32_t bhf[2], blf[2];
                uint32_t va = (uint32_t)((js*16 + l16)*208 + nv*16);
                lm2t(vb0 + va, bhf);
                lm2t(vb1 + va, blf);
                MMA(O[nv], pAh[js], bhf);
                MMA(O[nv], pAh[js], blf);
                MMA(O[nv], pAl[js], bhf);
            }
        }
        __syncthreads();
        if (kt + 2 < 8) loadKV(kt + 2, st);
    }

    l0 += __shfl_xor_sync(0xffffffffu, l0, 1);
    l0 += __shfl_xor_sync(0xffffffffu, l0, 2);
    l1 += __shfl_xor_sync(0xffffffffu, l1, 1);
    l1 += __shfl_xor_sync(0xffffffffu, l1, 2);
    float i0 = 1.f / l0, i1 = 1.f / l1;
    size_t gr0 = rowb + (size_t)qr0;
    size_t gr1 = gr0 + 8;
    int colb = h*DH + 2*(lane & 3);
    #pragma unroll
    for (int nv = 0; nv < 12; nv++) {
        uint32_t lo, hi;
        hi = packsplit(O[nv][0]*i0, O[nv][1]*i0, lo);
        *(uint32_t*)(g_att_h + gr0*Dd + colb + nv*8) = hi;
        *(uint32_t*)(g_att_l + gr0*Dd + colb + nv*8) = lo;
        hi = packsplit(O[nv][2]*i1, O[nv][3]*i1, lo);
        *(uint32_t*)(g_att_h + gr1*Dd + colb + nv*8) = hi;
        *(uint32_t*)(g_att_l + gr1*Dd + colb + nv*8) = lo;
    }
}

// ---------------- reductions ----------------
__device__ __forceinline__ float bsum(float v, float* sb) {
    int tid = threadIdx.x;
    #pragma unroll
    for (int o = 16; o > 0; o >>= 1) v += __shfl_down_sync(0xffffffffu, v, o);
    if ((tid & 31) == 0) sb[tid >> 5] = v;
    __syncthreads();
    float s = 0.f;
    if (tid < 32) {
        s = (tid < (int)(blockDim.x >> 5)) ? sb[tid] : 0.f;
        #pragma unroll
        for (int o = 16; o > 0; o >>= 1) s += __shfl_down_sync(0xffffffffu, s, o);
        if (tid == 0) sb[0] = s;
    }
    __syncthreads();
    float r = sb[0]; __syncthreads(); return r;
}

// ---------------- small kernels ----------------
__global__ void __launch_bounds__(256) cvt_split(const float* __restrict__ x,
                                                 bf16* __restrict__ hi, bf16* __restrict__ lo, int n4) {
    int i = blockIdx.x * 256 + threadIdx.x;
    if (i >= n4) return;
    float4 v = ((const float4*)x)[i];
    uint32_t l01, h01 = packsplit(v.x, v.y, l01);
    uint32_t l23, h23 = packsplit(v.z, v.w, l23);
    ((uint2*)hi)[i] = make_uint2(h01, h23);
    ((uint2*)lo)[i] = make_uint2(l01, l23);
}

__global__ void __launch_bounds__(256) rowstat_x(const float* __restrict__ x) {
    __shared__ float sb[32];
    int row = blockIdx.x, tid = threadIdx.x;
    float v[3];
    #pragma unroll
    for (int i = 0; i < 3; i++) v[i] = x[(size_t)row * Dd + tid + i * 256];
    float ss = bsum(v[0]*v[0] + v[1]*v[1] + v[2]*v[2], sb);
    int pad = (sqrtf(ss) <= 1e-6f) ? 1 : 0;
    if (tid == 0) { g_pad[row] = pad; g_xnorm[row] = pad ? 0.f : ss; g_padf[row] = pad ? NEGB : 0.f; }
    #pragma unroll
    for (int i = 0; i < 3; i++) {
        int c = tid + i * 256;
        float o = pad ? 0.f : v[i];
        g_mem[(size_t)row * Dd + c] = o;
        bf16 hh, ll; split2(o, hh, ll);
        g_mem_h[(size_t)row * Dd + c] = hh;
        g_mem_l[(size_t)row * Dd + c] = ll;
    }
}
__global__ void __launch_bounds__(256) rowstat_cb(const float* __restrict__ cb) {
    __shared__ float sb[32];
    int row = blockIdx.x, tid = threadIdx.x;
    float ss = 0.f;
    #pragma unroll
    for (int i = 0; i < 3; i++) { float v = cb[(size_t)row * Dd + tid + i * 256]; ss += v * v; }
    ss = bsum(ss, sb);
    if (tid == 0) g_cnorm[row] = ss;
}

// ---------------- layernorm (+split) ----------------
__global__ void __launch_bounds__(256) layernorm(const float* __restrict__ gam,
                                                 const float* __restrict__ bet) {
    __shared__ float sb[32];
    int row = blockIdx.x, tid = threadIdx.x;
    const float* x = g_tmp + (size_t)row * Dd;
    float v[3];
    #pragma unroll
    for (int i = 0; i < 3; i++) v[i] = x[tid + i * 256];
    float s = bsum(v[0] + v[1] + v[2], sb);
    float mean = s / 768.0f;
    float d2 = 0.f;
    #pragma unroll
    for (int i = 0; i < 3; i++) { float d = v[i] - mean; d2 += d * d; }
    d2 = bsum(d2, sb);
    float inv = 1.0f / sqrtf(d2 / 768.0f + 1e-5f);
    #pragma unroll
    for (int i = 0; i < 3; i++) {
        int c = tid + i * 256;
        float o = (v[i] - mean) * inv * gam[c] + bet[c];
        g_h[(size_t)row * Dd + c] = o;
        bf16 hh, ll; split2(o, hh, ll);
        g_h_h[(size_t)row * Dd + c] = hh;
        g_h_l[(size_t)row * Dd + c] = ll;
    }
}

// ---------------- threefry (JAX-exact) ----------------
__device__ __forceinline__ uint32_t rotl32(uint32_t x, int d) { return (x << d) | (x >> (32 - d)); }
__device__ void threefry2x32(uint32_t k0, uint32_t k1, uint32_t x0, uint32_t x1,
                             uint32_t& o0, uint32_t& o1) {
    uint32_t k2 = k0 ^ k1 ^ 0x1BD11BDAu;
    x0 += k0; x1 += k1;
    x0+=x1; x1=rotl32(x1,13); x1^=x0;  x0+=x1; x1=rotl32(x1,15); x1^=x0;
    x0+=x1; x1=rotl32(x1,26); x1^=x0;  x0+=x1; x1=rotl32(x1,6);  x1^=x0;
    x0 += k1; x1 += k2 + 1u;
    x0+=x1; x1=rotl32(x1,17); x1^=x0;  x0+=x1; x1=rotl32(x1,29); x1^=x0;
    x0+=x1; x1=rotl32(x1,16); x1^=x0;  x0+=x1; x1=rotl32(x1,24); x1^=x0;
    x0 += k2; x1 += k0 + 2u;
    x0+=x1; x1=rotl32(x1,13); x1^=x0;  x0+=x1; x1=rotl32(x1,15); x1^=x0;
    x0+=x1; x1=rotl32(x1,26); x1^=x0;  x0+=x1; x1=rotl32(x1,6);  x1^=x0;
    x0 += k0; x1 += k1 + 3u;
    x0+=x1; x1=rotl32(x1,17); x1^=x0;  x0+=x1; x1=rotl32(x1,29); x1^=x0;
    x0+=x1; x1=rotl32(x1,16); x1^=x0;  x0+=x1; x1=rotl32(x1,24); x1^=x0;
    x0 += k1; x1 += k2 + 4u;
    x0+=x1; x1=rotl32(x1,13); x1^=x0;  x0+=x1; x1=rotl32(x1,15); x1^=x0;
    x0+=x1; x1=rotl32(x1,26); x1^=x0;  x0+=x1; x1=rotl32(x1,6);  x1^=x0;
    x0 += k2; x1 += k0 + 5u;
    o0 = x0; o1 = x1;
}

// ---------------- VQ: approx top-12 -> exact fp32 rescore -> top-10 gumbel ----------------
__global__ void __launch_bounds__(256) vq_topk_refine(const float* __restrict__ cbf) {
    int row = blockIdx.x, tid = threadIdx.x;
    const float* __restrict__ drow = g_dist + (size_t)row * Kc;
    float td[12]; int ti[12];
    #pragma unroll
    for (int j = 0; j < 12; j++) { td[j] = 3.4e38f; ti[j] = 0x7fffffff; }
    for (int c = tid; c < Kc; c += 256) {
        float v = drow[c];
        if (v < td[11] || (v == td[11] && c < ti[11])) {
            int pos = 11;
            #pragma unroll
            for (int j = 10; j >= 0; j--) {
                bool lt = (v < td[j]) || (v == td[j] && c < ti[j]);
                if (lt) pos = j;
            }
            #pragma unroll
            for (int j = 11; j > 0; j--)
                if (j > pos) { td[j] = td[j-1]; ti[j] = ti[j-1]; }
            td[pos] = v; ti[pos] = c;
        }
    }
    __shared__ float sd[3072];
    __shared__ int   si[3072];
    __shared__ float ex[12];
    #pragma unroll
    for (int j = 0; j < 12; j++) { sd[tid*12+j] = td[j]; si[tid*12+j] = ti[j]; }
    for (int stride = 128; stride >= 1; stride >>= 1) {
        __syncthreads();
        if (tid < stride) {
            float od[12]; int oi[12];
            int a = 0, b2 = 0;
            #pragma unroll
            for (int j = 0; j < 12; j++) {
                float da = sd[tid*12+a], db = sd[(tid+stride)*12+b2];
                int   ia = si[tid*12+a], ib = si[(tid+stride)*12+b2];
                bool ta = (da < db) || (da == db && ia <= ib);
                if (ta) { od[j]=da; oi[j]=ia; a++; } else { od[j]=db; oi[j]=ib; b2++; }
            }
            #pragma unroll
            for (int j = 0; j < 12; j++) { sd[tid*12+j]=od[j]; si[tid*12+j]=oi[j]; }
        }
    }
    __syncthreads();
    int wid = tid >> 5, lane = tid & 31;
    const float* xr = g_mem + (size_t)row * Dd;
    for (int t = wid; t < 12; t += 8) {
        int ci = si[t];
        const float* cr = cbf + (size_t)ci * Dd;
        float s = 0.f;
        #pragma unroll
        for (int e = 0; e < 24; e++) s = fmaf(xr[lane + e*32], cr[lane + e*32], s);
        #pragma unroll
        for (int o = 16; o > 0; o >>= 1) s += __shfl_down_sync(0xffffffffu, s, o);
        if (lane == 0) ex[t] = (g_xnorm[row] + g_cnorm[ci]) - 2.f * s;
    }
    __syncthreads();
    if (tid == 0) {
        float dd[12]; int ii[12];
        #pragma unroll
        for (int j = 0; j < 12; j++) { dd[j] = ex[j]; ii[j] = si[j]; }
        #pragma unroll
        for (int a = 0; a < 10; a++) {
            int best = a;
            #pragma unroll
            for (int b2 = 0; b2 < 12; b2++) {
                if (b2 <= a) continue;
                bool lt = (dd[b2] < dd[best]) || (dd[b2] == dd[best] && ii[b2] < ii[best]);
                if (lt) best = b2;
            }
            float tdv = dd[a]; dd[a] = dd[best]; dd[best] = tdv;
            int tiv = ii[a]; ii[a] = ii[best]; ii[best] = tiv;
        }
        float bestv = -3.4e38f;
        int bi = ii[0];
        for (int j = 0; j < 10; j++) {
            uint32_t e = (uint32_t)(row * 10 + j);
            uint32_t o0, o1;
            threefry2x32(0u, 42u, 0u, e, o0, o1);
            uint32_t bits = o0 ^ o1;
            float u = __uint_as_float((bits >> 9) | 0x3f800000u) - 1.0f;
            u = fmaxf(1e-10f, u + 1e-10f);
            float gmb = -logf(-logf(u));
            float sc = -dd[j] + gmb;
            if (sc > bestv) { bestv = sc; bi = ii[j]; }
        }
        g_enc[row] = bi;
    }
}

__global__ void __launch_bounds__(256) vq_quantize(const float* __restrict__ cb) {
    int row = blockIdx.x, tid = threadIdx.x;
    int e = g_enc[row];
    #pragma unroll
    for (int i = 0; i < 3; i++) {
        int c = tid + i * 256;
        float z = g_mem[(size_t)row * Dd + c];
        float q = cb[(size_t)e * Dd + c];
        float o = z + (q - z);
        g_h[(size_t)row * Dd + c] = o;
        bf16 hh, ll; split2(o, hh, ll);
        g_h_h[(size_t)row * Dd + c] = hh;
        g_h_l[(size_t)row * Dd + c] = ll;
    }
}

// ---------------- host ----------------
static void* sym(const void* s) { void* p = nullptr; cudaGetSymbolAddress(&p, s); return p; }

extern "C" void kernel_launch(void* const* d_in, const int* in_sizes, int n_in,
                              void* d_out, int out_size) {
    const float* x     = (const float*)d_in[0];
    const float* cb    = (const float*)d_in[1];
    const float* sib   = (const float*)d_in[3];
    const float* sob   = (const float*)d_in[5];
    const float* cib   = (const float*)d_in[7];
    const float* cob   = (const float*)d_in[9];
    const float* ln1g  = (const float*)d_in[10];
    const float* ln1b  = (const float*)d_in[11];
    const float* ln2g  = (const float*)d_in[12];
    const float* ln2b  = (const float*)d_in[13];
    const float* ln3g  = (const float*)d_in[14];
    const float* ln3b  = (const float*)d_in[15];
    const float* fb1   = (const float*)d_in[17];
    const float* fb2   = (const float*)d_in[19];
    const float* outb  = (const float*)d_in[21];
    float* outp = (float*)d_out;

    cudaFuncSetAttribute(gemm_mma, cudaFuncAttributeMaxDynamicSharedMemorySize, GM_SMEM);
    cudaFuncSetAttribute(flash_attn, cudaFuncAttributeMaxDynamicSharedMemorySize, FA_SMEM);

    float* p_mem  = (float*)sym(g_mem);
    float* p_h    = (float*)sym(g_h);
    float* p_tmp  = (float*)sym(g_tmp);
    float* p_dist = (float*)sym(g_dist);
    float* p_xn   = (float*)sym(g_xnorm);
    float* p_cn   = (float*)sym(g_cnorm);
    bf16 *qkh = (bf16*)sym(g_qkvh), *qkl = (bf16*)sym(g_qkvl);
    bf16 *hh = (bf16*)sym(g_h_h),   *hl = (bf16*)sym(g_h_l);
    bf16 *ah = (bf16*)sym(g_att_h), *al = (bf16*)sym(g_att_l);
    bf16 *mh = (bf16*)sym(g_mem_h), *ml = (bf16*)sym(g_mem_l);
    bf16 *cbh = (bf16*)sym(g_cb_h), *cbl = (bf16*)sym(g_cb_l);
    bf16 *fh = (bf16*)sym(g_ff_h),  *fl = (bf16*)sym(g_ff_l);
    bf16 *wsa_h = (bf16*)sym(g_wsain_h),  *wsa_l = (bf16*)sym(g_wsain_l);
    bf16 *wso_h = (bf16*)sym(g_wsaout_h), *wso_l = (bf16*)sym(g_wsaout_l);
    bf16 *wca_h = (bf16*)sym(g_wcain_h),  *wca_l = (bf16*)sym(g_wcain_l);
    bf16 *wco_h = (bf16*)sym(g_wcaout_h), *wco_l = (bf16*)sym(g_wcaout_l);
    bf16 *wf1_h = (bf16*)sym(g_wff1_h),   *wf1_l = (bf16*)sym(g_wff1_l);
    bf16 *wf2_h = (bf16*)sym(g_wff2_h),   *wf2_l = (bf16*)sym(g_wff2_l);
    bf16 *wo_h  = (bf16*)sym(g_wout_h),   *wo_l  = (bf16*)sym(g_wout_l);

    auto CVT = [](const float* s, bf16* h, bf16* l, size_t n) {
        int n4 = (int)(n / 4);
        cvt_split<<<(n4 + 255) / 256, 256>>>(s, h, l, n4);
    };
    auto TG = [&](const bf16* Ah, const bf16* Al, const bf16* Wh, const bf16* Wl,
                  const float* bias, const float* resid, float* C, bf16* Ch, bf16* Cl,
                  int ldc, int N, int K, int mode) {
        dim3 grid(N / 256, NTOK / 128);
        gemm_mma<<<grid, 256, GM_SMEM>>>(Ah, Al, Wh, Wl, bias, resid, Dd, C, Ch, Cl, ldc, K, mode);
    };

    CVT((const float*)d_in[2],  wsa_h, wsa_l, (size_t)W_SAIN_N);
    CVT((const float*)d_in[4],  wso_h, wso_l, (size_t)W_SQ_N);
    CVT((const float*)d_in[6],  wca_h, wca_l, (size_t)W_SAIN_N);
    CVT((const float*)d_in[8],  wco_h, wco_l, (size_t)W_SQ_N);
    CVT((const float*)d_in[16], wf1_h, wf1_l, (size_t)W_FF1_N);
    CVT((const float*)d_in[18], wf2_h, wf2_l, (size_t)W_FF2_N);
    CVT((const float*)d_in[20], wo_h,  wo_l,  (size_t)W_OUT_N);
    CVT(cb, cbh, cbl, (size_t)Kc * Dd);

    // VQ: approx distances via 3-term HMMA, then exact fp32 rescore of top-12
    rowstat_x<<<NTOK, 256>>>(x);
    rowstat_cb<<<Kc, 256>>>(cb);
    TG(mh, ml, cbh, cbl, p_cn, p_xn, p_dist, nullptr, nullptr, Kc, Kc, Dd, 4);
    vq_topk_refine<<<NTOK, 256>>>(cb);
    vq_quantize<<<NTOK, 256>>>(cb);

    for (int l = 0; l < Ll; l++) {
        size_t win = (size_t)l * 3 * Dd * Dd, wsq = (size_t)l * Dd * Dd;
        // self-attention (N = 2304 = 9 * 256)
        TG(hh, hl, wsa_h + win, wsa_l + win, sib + (size_t)l*3*Dd, nullptr,
           nullptr, qkh, qkl, 3*Dd, 3*Dd, Dd, 3);
        flash_attn<<<dim3(4, Bb*Hh), 256, FA_SMEM>>>(1);
        TG(ah, al, wso_h + wsq, wso_l + wsq, sob + (size_t)l*Dd, p_h,
           p_tmp, nullptr, nullptr, Dd, Dd, Dd, 2);
        layernorm<<<NTOK, 256>>>(ln1g + (size_t)l*Dd, ln1b + (size_t)l*Dd);

        // cross-attention: Q from h (N=768), K/V from mem (N=1536)
        TG(hh, hl, wca_h + win, wca_l + win, cib + (size_t)l*3*Dd, nullptr,
           nullptr, qkh, qkl, 3*Dd, Dd, Dd, 3);
        TG(mh, ml, wca_h + win + (size_t)Dd*Dd, wca_l + win + (size_t)Dd*Dd,
           cib + (size_t)l*3*Dd + Dd, nullptr,
           nullptr, qkh + Dd, qkl + Dd, 3*Dd, 2*Dd, Dd, 3);
        flash_attn<<<dim3(4, Bb*Hh), 256, FA_SMEM>>>(0);
        TG(ah, al, wco_h + wsq, wco_l + wsq, cob + (size_t)l*Dd, p_h,
           p_tmp, nullptr, nullptr, Dd, Dd, Dd, 2);
        layernorm<<<NTOK, 256>>>(ln2g + (size_t)l*Dd, ln2b + (size_t)l*Dd);

        // feed-forward
        TG(hh, hl, wf1_h + (size_t)l*FFd*Dd, wf1_l + (size_t)l*FFd*Dd,
           fb1 + (size_t)l*FFd, nullptr, nullptr, fh, fl, FFd, FFd, Dd, 1);
        TG(fh, fl, wf2_h + (size_t)l*Dd*FFd, wf2_l + (size_t)l*Dd*FFd,
           fb2 + (size_t)l*Dd, p_h, p_tmp, nullptr, nullptr, Dd, Dd, FFd, 2);
        layernorm<<<NTOK, 256>>>(ln3g + (size_t)l*Dd, ln3b + (size_t)l*Dd);
    }

    TG(hh, hl, wo_h, wo_l, outb, nullptr, outp, nullptr, nullptr, Dd, Dd, Dd, 0);
}